// round 16
// baseline (speedup 1.0000x reference)
#include <cuda_runtime.h>
#include <cuda_bf16.h>
#include <cstdint>

#define IN_F   768
#define HID    16
#define OUTF   21
#define NMAX   50000
#define CAP    96
#define NKS    48              // k-steps of 16

// Scratch (no cudaMalloc allowed)
__device__ float g_xp  [NMAX * HID];
__device__ float g_h1  [NMAX * HID];
__device__ int   g_cnt [NMAX];
__device__ int   g_bin [NMAX * CAP];
__device__ uint2 g_bfrag[NKS * 2 * 2 * 32];   // [kstep][nt][hilo][lane]
__device__ int   g_tile;                      // persistent-kernel tile counter

// ---------------- helpers ----------------
__device__ __forceinline__ void cvt_hilo(float a, float b, uint32_t& hi, uint32_t& lo) {
    __nv_bfloat16 ha = __float2bfloat16(a), hb = __float2bfloat16(b);
    __nv_bfloat16 la = __float2bfloat16(a - __bfloat162float(ha));
    __nv_bfloat16 lb = __float2bfloat16(b - __bfloat162float(hb));
    __nv_bfloat162 h = __halves2bfloat162(ha, hb);
    __nv_bfloat162 l = __halves2bfloat162(la, lb);
    hi = *(uint32_t*)&h;
    lo = *(uint32_t*)&l;
}

__device__ __forceinline__ void mma_bf16(float* d, uint32_t a0, uint32_t a1,
                                         uint32_t a2, uint32_t a3,
                                         uint32_t b0, uint32_t b1) {
    asm volatile(
        "mma.sync.aligned.m16n8k16.row.col.f32.bf16.bf16.f32 "
        "{%0,%1,%2,%3}, {%4,%5,%6,%7}, {%8,%9}, {%0,%1,%2,%3};"
        : "+f"(d[0]), "+f"(d[1]), "+f"(d[2]), "+f"(d[3])
        : "r"(a0), "r"(a1), "r"(a2), "r"(a3), "r"(b0), "r"(b1));
}

// ---------------- K1: zero counters + tile counter + build B fragments ------
__global__ __launch_bounds__(256) void k_prep(
    const float* __restrict__ W1, uint2* __restrict__ bf,
    int* __restrict__ cnt, int* __restrict__ tileCnt, int nNodes)
{
    int i = blockIdx.x * blockDim.x + threadIdx.x;
    if (i == 0) *tileCnt = 0;
    if (i < nNodes) cnt[i] = 0;
    if (i < NKS * 2 * 2 * 32) {
        int lane = i & 31;
        int hilo = (i >> 5) & 1;
        int nt   = (i >> 6) & 1;
        int ks   = i >> 7;
        int n  = nt * 8 + (lane >> 2);
        int k0 = ks * 16 + (lane & 3) * 2;
        float v0 = W1[(k0 + 0) * HID + n];
        float v1 = W1[(k0 + 1) * HID + n];
        float v2 = W1[(k0 + 8) * HID + n];
        float v3 = W1[(k0 + 9) * HID + n];
        uint32_t h01, l01, h23, l23;
        cvt_hilo(v0, v1, h01, l01);
        cvt_hilo(v2, v3, h23, l23);
        bf[i] = hilo ? make_uint2(l01, l23) : make_uint2(h01, h23);
    }
}

// ---------------- K2: fill bins ----------------
__global__ __launch_bounds__(256) void k_fill(
    const int* __restrict__ src, const int* __restrict__ dst,
    int* __restrict__ cnt, int* __restrict__ bin, int nE)
{
    int e = blockIdx.x * blockDim.x + threadIdx.x;
    if (e >= nE) return;
    int s = src[e], d = dst[e];
    int slot = atomicAdd(&cnt[d], 1);
    if (slot < CAP) bin[d * CAP + slot] = s;
}

// ---------------- K3: Xp = F @ W1, mma.sync bf16x3, persistent + stealing ---
// Proven R13 core (256 thr, 48KB static smem, 64 regs, ring prefetch).
// Grid = 2/SM persistent blocks; tiles of 128 rows pulled from g_tile.
__global__ __launch_bounds__(256) void k_gemm1(
    const float* __restrict__ F, const uint2* __restrict__ bfrag,
    float* __restrict__ Xp, int* __restrict__ tileCnt,
    int nNodes, int nTiles)
{
    __shared__ uint2 Bs[NKS * 2 * 2 * 32];    // 48 KB
    __shared__ int tile_s;

    const int tid = threadIdx.x, lane = tid & 31, warp = tid >> 5;

    {
        const uint4* s4 = (const uint4*)bfrag;
        uint4* d4 = (uint4*)Bs;
        #pragma unroll
        for (int i = 0; i < 12; i++) d4[i * 256 + tid] = s4[i * 256 + tid];
    }

    for (;;) {
        __syncthreads();                       // guards tile_s + Bs staging
        if (tid == 0) tile_s = atomicAdd(tileCnt, 1);
        __syncthreads();
        int tile = tile_s;
        if (tile >= nTiles) break;

        int rb = tile * 128;
        if (rb > nNodes - 128) rb = nNodes - 128;
        const int rw0 = rb + warp * 16;

        const float* p0 = F + (size_t)(rw0 + (lane >> 2)) * IN_F + (lane & 3) * 2;
        const float* p1 = p0 + 8 * IN_F;
        const float* p2 = p0 + 8;
        const float* p3 = p1 + 8;

        float2 pre[2][4];
        #pragma unroll
        for (int b = 0; b < 2; b++) {
            int off = b * 16;
            pre[b][0] = __ldg((const float2*)(p0 + off));
            pre[b][1] = __ldg((const float2*)(p1 + off));
            pre[b][2] = __ldg((const float2*)(p2 + off));
            pre[b][3] = __ldg((const float2*)(p3 + off));
        }

        float acc[2][4] = {{0.f, 0.f, 0.f, 0.f}, {0.f, 0.f, 0.f, 0.f}};

        for (int s = 0; s < NKS; s++) {
            const int pb = s & 1;
            uint32_t ah[4], al[4];
            #pragma unroll
            for (int j = 0; j < 4; j++)
                cvt_hilo(pre[pb][j].x, pre[pb][j].y, ah[j], al[j]);

            if (s + 2 < NKS) {
                int off = (s + 2) * 16;
                pre[pb][0] = __ldg((const float2*)(p0 + off));
                pre[pb][1] = __ldg((const float2*)(p1 + off));
                pre[pb][2] = __ldg((const float2*)(p2 + off));
                pre[pb][3] = __ldg((const float2*)(p3 + off));
            }

            #pragma unroll
            for (int nt = 0; nt < 2; nt++) {
                uint2 bh = Bs[((s * 2 + nt) * 2 + 0) * 32 + lane];
                uint2 bl = Bs[((s * 2 + nt) * 2 + 1) * 32 + lane];
                mma_bf16(acc[nt], ah[0], ah[1], ah[2], ah[3], bh.x, bh.y);
                mma_bf16(acc[nt], ah[0], ah[1], ah[2], ah[3], bl.x, bl.y);
                mma_bf16(acc[nt], al[0], al[1], al[2], al[3], bh.x, bh.y);
            }
        }

        int r0 = rw0 + (lane >> 2);
        #pragma unroll
        for (int nt = 0; nt < 2; nt++) {
            int c0 = nt * 8 + (lane & 3) * 2;
            *(float2*)(Xp + (size_t)r0 * HID + c0)       = make_float2(acc[nt][0], acc[nt][1]);
            *(float2*)(Xp + (size_t)(r0 + 8) * HID + c0) = make_float2(acc[nt][2], acc[nt][3]);
        }
    }
}

// ---------------- K4: gather1 -> h1 = relu(sum(Xp[bin]) + b1) ----------------
__global__ __launch_bounds__(256) void k_gather1(
    const float* __restrict__ xin, float* __restrict__ xout,
    const int* __restrict__ cnt, const int* __restrict__ bin,
    const float* __restrict__ b1, int nNodes)
{
    int t = blockIdx.x * 256 + threadIdx.x;
    int n  = t >> 2;
    int qd = t & 3;
    if (n >= nNodes) return;

    int c = cnt[n]; if (c > CAP) c = CAP;
    const int* bp = bin + n * CAP;
    float4 acc = make_float4(0.f, 0.f, 0.f, 0.f);

    int i = 0;
    for (; i + 4 <= c; i += 4) {
        int s0 = bp[i], s1 = bp[i+1], s2 = bp[i+2], s3 = bp[i+3];
        float4 a = __ldg((const float4*)(xin + (size_t)s0 * HID) + qd);
        float4 b = __ldg((const float4*)(xin + (size_t)s1 * HID) + qd);
        float4 d = __ldg((const float4*)(xin + (size_t)s2 * HID) + qd);
        float4 e = __ldg((const float4*)(xin + (size_t)s3 * HID) + qd);
        acc.x += (a.x + b.x) + (d.x + e.x);
        acc.y += (a.y + b.y) + (d.y + e.y);
        acc.z += (a.z + b.z) + (d.z + e.z);
        acc.w += (a.w + b.w) + (d.w + e.w);
    }
    for (; i < c; i++) {
        int s0 = bp[i];
        float4 a = __ldg((const float4*)(xin + (size_t)s0 * HID) + qd);
        acc.x += a.x; acc.y += a.y; acc.z += a.z; acc.w += a.w;
    }

    float4 b = __ldg((const float4*)b1 + qd);
    float4 o;
    o.x = fmaxf(acc.x + b.x, 0.f);
    o.y = fmaxf(acc.y + b.y, 0.f);
    o.z = fmaxf(acc.z + b.z, 0.f);
    o.w = fmaxf(acc.w + b.w, 0.f);
    *((float4*)(xout + (size_t)n * HID) + qd) = o;
}

// ---------------- K5: out = gather2(h1) @ W2 + b2 (fused) ----------------
__global__ __launch_bounds__(256) void k_out(
    const float* __restrict__ h1, const int* __restrict__ cnt,
    const int* __restrict__ bin, const float* __restrict__ W2,
    const float* __restrict__ b2, float* __restrict__ out, int nNodes)
{
    __shared__ float Ws[HID * OUTF];
    __shared__ float bs[OUTF];
    int tid = threadIdx.x;
    for (int i = tid; i < HID * OUTF; i += 256) Ws[i] = W2[i];
    if (tid < OUTF) bs[tid] = b2[tid];
    __syncthreads();

    int t = blockIdx.x * 256 + tid;
    int n  = t >> 2;
    int qd = t & 3;
    bool valid = (n < nNodes);
    int nc = valid ? n : (nNodes - 1);

    int c = cnt[nc]; if (c > CAP) c = CAP;
    const int* bp = bin + nc * CAP;
    float4 acc = make_float4(0.f, 0.f, 0.f, 0.f);

    int i = 0;
    for (; i + 4 <= c; i += 4) {
        int s0 = bp[i], s1 = bp[i+1], s2 = bp[i+2], s3 = bp[i+3];
        float4 a = __ldg((const float4*)(h1 + (size_t)s0 * HID) + qd);
        float4 b = __ldg((const float4*)(h1 + (size_t)s1 * HID) + qd);
        float4 d = __ldg((const float4*)(h1 + (size_t)s2 * HID) + qd);
        float4 e = __ldg((const float4*)(h1 + (size_t)s3 * HID) + qd);
        acc.x += (a.x + b.x) + (d.x + e.x);
        acc.y += (a.y + b.y) + (d.y + e.y);
        acc.z += (a.z + b.z) + (d.z + e.z);
        acc.w += (a.w + b.w) + (d.w + e.w);
    }
    for (; i < c; i++) {
        int s0 = bp[i];
        float4 a = __ldg((const float4*)(h1 + (size_t)s0 * HID) + qd);
        acc.x += a.x; acc.y += a.y; acc.z += a.z; acc.w += a.w;
    }

    float hv[16];
    hv[qd * 4 + 0] = acc.x;
    hv[qd * 4 + 1] = acc.y;
    hv[qd * 4 + 2] = acc.z;
    hv[qd * 4 + 3] = acc.w;
    #pragma unroll
    for (int d = 1; d < 4; d++) {
        int oq = qd ^ d;
        hv[oq * 4 + 0] = __shfl_xor_sync(0xffffffffu, acc.x, d);
        hv[oq * 4 + 1] = __shfl_xor_sync(0xffffffffu, acc.y, d);
        hv[oq * 4 + 2] = __shfl_xor_sync(0xffffffffu, acc.z, d);
        hv[oq * 4 + 3] = __shfl_xor_sync(0xffffffffu, acc.w, d);
    }

    if (valid) {
        float* op = out + (size_t)n * OUTF;
        #pragma unroll
        for (int j0 = 0; j0 < OUTF; j0 += 4) {
            int j = j0 + qd;
            if (j < OUTF) {
                float a = bs[j];
                #pragma unroll
                for (int k = 0; k < HID; k++)
                    a = fmaf(hv[k], Ws[k * OUTF + j], a);
                op[j] = a;
            }
        }
    }
}

// ---------------- launch ----------------
extern "C" void kernel_launch(void* const* d_in, const int* in_sizes, int n_in,
                              void* d_out, int out_size)
{
    const float* feature = (const float*)d_in[0];
    const float* W1      = (const float*)d_in[1];
    const float* b1      = (const float*)d_in[2];
    const float* W2      = (const float*)d_in[3];
    const float* b2      = (const float*)d_in[4];
    const int*   src     = (const int*)  d_in[5];
    const int*   dst     = (const int*)  d_in[6];
    float*       out     = (float*)d_out;

    int nNodes = in_sizes[0] / IN_F;
    if (nNodes > NMAX) nNodes = NMAX;
    int nE = in_sizes[5];

    float *xp, *h1;
    int *cnt, *bin, *tileCnt;
    uint2* bfrag;
    cudaGetSymbolAddress((void**)&xp,      g_xp);
    cudaGetSymbolAddress((void**)&h1,      g_h1);
    cudaGetSymbolAddress((void**)&cnt,     g_cnt);
    cudaGetSymbolAddress((void**)&bin,     g_bin);
    cudaGetSymbolAddress((void**)&bfrag,   g_bfrag);
    cudaGetSymbolAddress((void**)&tileCnt, g_tile);

    k_prep<<<(nNodes + 255) / 256, 256>>>(W1, bfrag, cnt, tileCnt, nNodes);  // #1

    k_fill<<<(nE + 255) / 256, 256>>>(src, dst, cnt, bin, nE);               // #2

    int nTiles = (nNodes + 127) / 128;
    int pgrid = 296;                         // 2 persistent blocks per SM
    if (pgrid > nTiles) pgrid = nTiles;
    k_gemm1<<<pgrid, 256>>>(feature, bfrag, xp, tileCnt, nNodes, nTiles);    // #3

    int gblk = (nNodes * 4 + 255) / 256;
    k_gather1<<<gblk, 256>>>(xp, h1, cnt, bin, b1, nNodes);                  // #4 (profiled)

    k_out<<<gblk, 256>>>(h1, cnt, bin, W2, b2, out, nNodes);                 // #5
}

// round 17
// speedup vs baseline: 1.2806x; 1.2806x over previous
#include <cuda_runtime.h>
#include <cuda_bf16.h>
#include <cstdint>

#define IN_F   768
#define HID    16
#define OUTF   21
#define NMAX   50000
#define CAP    96
#define NKS    48              // k-steps of 16

// Scratch (no cudaMalloc allowed)
__device__ float g_xp  [NMAX * HID];
__device__ float g_h1  [NMAX * HID];
__device__ int   g_cnt [NMAX];
__device__ int   g_bin [NMAX * CAP];
__device__ uint2 g_bfrag[NKS * 2 * 2 * 32];   // [kstep][nt][hilo][lane]

// ---------------- helpers ----------------
__device__ __forceinline__ void cvt_hilo(float a, float b, uint32_t& hi, uint32_t& lo) {
    __nv_bfloat16 ha = __float2bfloat16(a), hb = __float2bfloat16(b);
    __nv_bfloat16 la = __float2bfloat16(a - __bfloat162float(ha));
    __nv_bfloat16 lb = __float2bfloat16(b - __bfloat162float(hb));
    __nv_bfloat162 h = __halves2bfloat162(ha, hb);
    __nv_bfloat162 l = __halves2bfloat162(la, lb);
    hi = *(uint32_t*)&h;
    lo = *(uint32_t*)&l;
}

__device__ __forceinline__ void mma_bf16(float* d, uint32_t a0, uint32_t a1,
                                         uint32_t a2, uint32_t a3,
                                         uint32_t b0, uint32_t b1) {
    asm volatile(
        "mma.sync.aligned.m16n8k16.row.col.f32.bf16.bf16.f32 "
        "{%0,%1,%2,%3}, {%4,%5,%6,%7}, {%8,%9}, {%0,%1,%2,%3};"
        : "+f"(d[0]), "+f"(d[1]), "+f"(d[2]), "+f"(d[3])
        : "r"(a0), "r"(a1), "r"(a2), "r"(a3), "r"(b0), "r"(b1));
}

// ---------------- K1: zero counters + build B fragments ----------------
__global__ __launch_bounds__(256) void k_prep(
    const float* __restrict__ W1, uint2* __restrict__ bf,
    int* __restrict__ cnt, int nNodes)
{
    int i = blockIdx.x * blockDim.x + threadIdx.x;
    if (i < nNodes) cnt[i] = 0;
    if (i < NKS * 2 * 2 * 32) {
        int lane = i & 31;
        int hilo = (i >> 5) & 1;
        int nt   = (i >> 6) & 1;
        int ks   = i >> 7;
        int n  = nt * 8 + (lane >> 2);
        int k0 = ks * 16 + (lane & 3) * 2;
        float v0 = W1[(k0 + 0) * HID + n];
        float v1 = W1[(k0 + 1) * HID + n];
        float v2 = W1[(k0 + 8) * HID + n];
        float v3 = W1[(k0 + 9) * HID + n];
        uint32_t h01, l01, h23, l23;
        cvt_hilo(v0, v1, h01, l01);
        cvt_hilo(v2, v3, h23, l23);
        bf[i] = hilo ? make_uint2(l01, l23) : make_uint2(h01, h23);
    }
}

// ---------------- K2: fill bins ----------------
__global__ __launch_bounds__(256) void k_fill(
    const int* __restrict__ src, const int* __restrict__ dst,
    int* __restrict__ cnt, int* __restrict__ bin, int nE)
{
    int e = blockIdx.x * blockDim.x + threadIdx.x;
    if (e >= nE) return;
    int s = src[e], d = dst[e];
    int slot = atomicAdd(&cnt[d], 1);
    if (slot < CAP) bin[d * CAP + slot] = s;
}

// ---------------- K3: Xp = F @ W1, mma.sync bf16x3 (FROZEN R12 core) --------
__global__ __launch_bounds__(256) void k_gemm1(
    const float* __restrict__ F, const uint2* __restrict__ bfrag,
    float* __restrict__ Xp, int nNodes)
{
    __shared__ uint2 Bs[NKS * 2 * 2 * 32];    // 48 KB

    const int tid = threadIdx.x, lane = tid & 31, warp = tid >> 5;

    {
        const uint4* s4 = (const uint4*)bfrag;
        uint4* d4 = (uint4*)Bs;
        #pragma unroll
        for (int i = 0; i < 12; i++) d4[i * 256 + tid] = s4[i * 256 + tid];
    }
    __syncthreads();

    int rb = blockIdx.x * 128;
    if (rb > nNodes - 128) rb = nNodes - 128;
    const int rw0 = rb + warp * 16;

    const float* p0 = F + (size_t)(rw0 + (lane >> 2)) * IN_F + (lane & 3) * 2;
    const float* p1 = p0 + 8 * IN_F;
    const float* p2 = p0 + 8;
    const float* p3 = p1 + 8;

    float2 pre[2][4];
    #pragma unroll
    for (int b = 0; b < 2; b++) {
        int off = b * 16;
        pre[b][0] = __ldg((const float2*)(p0 + off));
        pre[b][1] = __ldg((const float2*)(p1 + off));
        pre[b][2] = __ldg((const float2*)(p2 + off));
        pre[b][3] = __ldg((const float2*)(p3 + off));
    }

    float acc[2][4] = {{0.f, 0.f, 0.f, 0.f}, {0.f, 0.f, 0.f, 0.f}};

    for (int s = 0; s < NKS; s++) {
        const int pb = s & 1;
        uint32_t ah[4], al[4];
        #pragma unroll
        for (int j = 0; j < 4; j++)
            cvt_hilo(pre[pb][j].x, pre[pb][j].y, ah[j], al[j]);

        if (s + 2 < NKS) {
            int off = (s + 2) * 16;
            pre[pb][0] = __ldg((const float2*)(p0 + off));
            pre[pb][1] = __ldg((const float2*)(p1 + off));
            pre[pb][2] = __ldg((const float2*)(p2 + off));
            pre[pb][3] = __ldg((const float2*)(p3 + off));
        }

        #pragma unroll
        for (int nt = 0; nt < 2; nt++) {
            uint2 bh = Bs[((s * 2 + nt) * 2 + 0) * 32 + lane];
            uint2 bl = Bs[((s * 2 + nt) * 2 + 1) * 32 + lane];
            mma_bf16(acc[nt], ah[0], ah[1], ah[2], ah[3], bh.x, bh.y);
            mma_bf16(acc[nt], ah[0], ah[1], ah[2], ah[3], bl.x, bl.y);
            mma_bf16(acc[nt], al[0], al[1], al[2], al[3], bh.x, bh.y);
        }
    }

    int r0 = rw0 + (lane >> 2);
    #pragma unroll
    for (int nt = 0; nt < 2; nt++) {
        int c0 = nt * 8 + (lane & 3) * 2;
        *(float2*)(Xp + (size_t)r0 * HID + c0)       = make_float2(acc[nt][0], acc[nt][1]);
        *(float2*)(Xp + (size_t)(r0 + 8) * HID + c0) = make_float2(acc[nt][2], acc[nt][3]);
    }
}

// ---------------- K4: gather1, 8 threads/node ----------------
// lane group = n*8 + sub*4 + qd. sub in {0,1} splits bin list by parity;
// shfl_xor(4) combines halves. Clamp (no early return) keeps masks full.
__global__ __launch_bounds__(256) void k_gather1(
    const float* __restrict__ xin, float* __restrict__ xout,
    const int* __restrict__ cnt, const int* __restrict__ bin,
    const float* __restrict__ b1, int nNodes)
{
    int t = blockIdx.x * 256 + threadIdx.x;
    int n   = t >> 3;
    int sub = (t >> 2) & 1;
    int qd  = t & 3;
    bool valid = (n < nNodes);
    int nc = valid ? n : (nNodes - 1);

    int c = cnt[nc]; if (c > CAP) c = CAP;
    const int* bp = bin + nc * CAP;
    float4 acc = make_float4(0.f, 0.f, 0.f, 0.f);

    int i = sub;
    for (; i + 2 < c; i += 4) {
        int s0 = bp[i], s1 = bp[i + 2];
        float4 a = __ldg((const float4*)(xin + (size_t)s0 * HID) + qd);
        float4 b = __ldg((const float4*)(xin + (size_t)s1 * HID) + qd);
        acc.x += a.x + b.x; acc.y += a.y + b.y;
        acc.z += a.z + b.z; acc.w += a.w + b.w;
    }
    for (; i < c; i += 2) {
        int s0 = bp[i];
        float4 a = __ldg((const float4*)(xin + (size_t)s0 * HID) + qd);
        acc.x += a.x; acc.y += a.y; acc.z += a.z; acc.w += a.w;
    }

    // combine parity halves
    acc.x += __shfl_xor_sync(0xffffffffu, acc.x, 4);
    acc.y += __shfl_xor_sync(0xffffffffu, acc.y, 4);
    acc.z += __shfl_xor_sync(0xffffffffu, acc.z, 4);
    acc.w += __shfl_xor_sync(0xffffffffu, acc.w, 4);

    if (valid && sub == 0) {
        float4 b = __ldg((const float4*)b1 + qd);
        float4 o;
        o.x = fmaxf(acc.x + b.x, 0.f);
        o.y = fmaxf(acc.y + b.y, 0.f);
        o.z = fmaxf(acc.z + b.z, 0.f);
        o.w = fmaxf(acc.w + b.w, 0.f);
        *((float4*)(xout + (size_t)n * HID) + qd) = o;
    }
}

// ---------------- K5: out = gather2(h1) @ W2 + b2, 8 threads/node ----------
__global__ __launch_bounds__(256) void k_out(
    const float* __restrict__ h1, const int* __restrict__ cnt,
    const int* __restrict__ bin, const float* __restrict__ W2,
    const float* __restrict__ b2, float* __restrict__ out, int nNodes)
{
    __shared__ float Ws[HID * OUTF];
    __shared__ float bs[OUTF];
    int tid = threadIdx.x;
    for (int i = tid; i < HID * OUTF; i += 256) Ws[i] = W2[i];
    if (tid < OUTF) bs[tid] = b2[tid];
    __syncthreads();

    int t = blockIdx.x * 256 + tid;
    int n   = t >> 3;
    int sub = (t >> 2) & 1;
    int qd  = t & 3;
    bool valid = (n < nNodes);
    int nc = valid ? n : (nNodes - 1);

    int c = cnt[nc]; if (c > CAP) c = CAP;
    const int* bp = bin + nc * CAP;
    float4 acc = make_float4(0.f, 0.f, 0.f, 0.f);

    int i = sub;
    for (; i + 2 < c; i += 4) {
        int s0 = bp[i], s1 = bp[i + 2];
        float4 a = __ldg((const float4*)(h1 + (size_t)s0 * HID) + qd);
        float4 b = __ldg((const float4*)(h1 + (size_t)s1 * HID) + qd);
        acc.x += a.x + b.x; acc.y += a.y + b.y;
        acc.z += a.z + b.z; acc.w += a.w + b.w;
    }
    for (; i < c; i += 2) {
        int s0 = bp[i];
        float4 a = __ldg((const float4*)(h1 + (size_t)s0 * HID) + qd);
        acc.x += a.x; acc.y += a.y; acc.z += a.z; acc.w += a.w;
    }

    // combine parity halves (both subs end with full sums)
    acc.x += __shfl_xor_sync(0xffffffffu, acc.x, 4);
    acc.y += __shfl_xor_sync(0xffffffffu, acc.y, 4);
    acc.z += __shfl_xor_sync(0xffffffffu, acc.z, 4);
    acc.w += __shfl_xor_sync(0xffffffffu, acc.w, 4);

    // assemble full 16-vector within the 4-lane quad (xor 1,2,3 stay in quad)
    float hv[16];
    hv[qd * 4 + 0] = acc.x;
    hv[qd * 4 + 1] = acc.y;
    hv[qd * 4 + 2] = acc.z;
    hv[qd * 4 + 3] = acc.w;
    #pragma unroll
    for (int d = 1; d < 4; d++) {
        int oq = qd ^ d;
        hv[oq * 4 + 0] = __shfl_xor_sync(0xffffffffu, acc.x, d);
        hv[oq * 4 + 1] = __shfl_xor_sync(0xffffffffu, acc.y, d);
        hv[oq * 4 + 2] = __shfl_xor_sync(0xffffffffu, acc.z, d);
        hv[oq * 4 + 3] = __shfl_xor_sync(0xffffffffu, acc.w, d);
    }

    if (valid) {
        int sid = sub * 4 + qd;                  // 0..7: split 21 cols 8-ways
        float* op = out + (size_t)n * OUTF;
        #pragma unroll
        for (int j = sid; j < OUTF; j += 8) {
            float a = bs[j];
            #pragma unroll
            for (int k = 0; k < HID; k++)
                a = fmaf(hv[k], Ws[k * OUTF + j], a);
            op[j] = a;
        }
    }
}

// ---------------- launch ----------------
extern "C" void kernel_launch(void* const* d_in, const int* in_sizes, int n_in,
                              void* d_out, int out_size)
{
    const float* feature = (const float*)d_in[0];
    const float* W1      = (const float*)d_in[1];
    const float* b1      = (const float*)d_in[2];
    const float* W2      = (const float*)d_in[3];
    const float* b2      = (const float*)d_in[4];
    const int*   src     = (const int*)  d_in[5];
    const int*   dst     = (const int*)  d_in[6];
    float*       out     = (float*)d_out;

    int nNodes = in_sizes[0] / IN_F;
    if (nNodes > NMAX) nNodes = NMAX;
    int nE = in_sizes[5];

    float *xp, *h1;
    int *cnt, *bin;
    uint2* bfrag;
    cudaGetSymbolAddress((void**)&xp,    g_xp);
    cudaGetSymbolAddress((void**)&h1,    g_h1);
    cudaGetSymbolAddress((void**)&cnt,   g_cnt);
    cudaGetSymbolAddress((void**)&bin,   g_bin);
    cudaGetSymbolAddress((void**)&bfrag, g_bfrag);

    k_prep<<<(nNodes + 255) / 256, 256>>>(W1, bfrag, cnt, nNodes);      // #1

    k_fill<<<(nE + 255) / 256, 256>>>(src, dst, cnt, bin, nE);          // #2

    k_gemm1<<<(nNodes + 127) / 128, 256>>>(feature, bfrag, xp, nNodes); // #3

    int gblk = (nNodes * 8 + 255) / 256;
    k_gather1<<<gblk, 256>>>(xp, h1, cnt, bin, b1, nNodes);             // #4 (profiled)

    k_out<<<gblk, 256>>>(h1, cnt, bin, W2, b2, out, nNodes);            // #5
}